// round 4
// baseline (speedup 1.0000x reference)
#include <cuda_runtime.h>
#include <cstdint>

#define BATCH 16
#define CCH   512
#define NPIX  4096

// attention / energy scratch: 16 MB
__device__ float g_energy[(size_t)BATCH * CCH * CCH];

// ---------------------------------------------------------------------------
// helpers
// ---------------------------------------------------------------------------
__device__ __forceinline__ uint32_t hi_tf32(float x) {
    return __float_as_uint(x) & 0xFFFFE000u;   // exact tf32 (top 19 bits)
}
__device__ __forceinline__ uint32_t lo_tf32(float x, uint32_t hibits) {
    float lo = x - __uint_as_float(hibits);
    uint32_t r;
    asm("cvt.rna.tf32.f32 %0, %1;" : "=r"(r) : "f"(lo));
    return r;
}
__device__ __forceinline__ void mma8(float* d, const uint32_t* a, const uint32_t* b) {
    asm volatile(
        "mma.sync.aligned.m16n8k8.row.col.f32.tf32.tf32.f32 "
        "{%0,%1,%2,%3}, {%4,%5,%6,%7}, {%8,%9}, {%0,%1,%2,%3};"
        : "+f"(d[0]), "+f"(d[1]), "+f"(d[2]), "+f"(d[3])
        : "r"(a[0]), "r"(a[1]), "r"(a[2]), "r"(a[3]), "r"(b[0]), "r"(b[1]));
}
__device__ __forceinline__ void split_store(uint32_t* dH, uint32_t* dL, float4 v) {
    uint4 h, l;
    h.x = hi_tf32(v.x); h.y = hi_tf32(v.y); h.z = hi_tf32(v.z); h.w = hi_tf32(v.w);
    l.x = lo_tf32(v.x, h.x); l.y = lo_tf32(v.y, h.y);
    l.z = lo_tf32(v.z, h.z); l.w = lo_tf32(v.w, h.w);
    *(uint4*)dH = h;
    *(uint4*)dL = l;
}

#define RS 36                 // m-major row stride (floats), conflict-free
#define ET (128 * RS)         // 4608 u32 per 128x32 tile

// ---------------------------------------------------------------------------
// Kernel 1: energy[b] = q qᵀ  (3xTF32, symmetric: 10 upper blocks + mirror)
// 512 thr, warps 4x4, warp tile 32x32, BK=32, double-buffered hi/lo smem.
// ---------------------------------------------------------------------------
#define ESTAGE (4 * ET)                   // AH|AL|BH|BL = 18432 u32
#define ESMEM_BYTES (2 * ESTAGE * 4)      // 147456

__global__ __launch_bounds__(512) void energy_kernel(const float* __restrict__ x)
{
    extern __shared__ uint32_t sm[];
    const int tid = threadIdx.x, lane = tid & 31, wid = tid >> 5;
    const int b = blockIdx.y;

    // upper-triangle pair (bi <= bj) from blockIdx.x in [0,10)
    int bi = 0, t = blockIdx.x, rowlen = 4;
    while (t >= rowlen) { t -= rowlen; bi++; rowlen--; }
    const int bj = bi + t;

    const float* q = x + (size_t)b * CCH * NPIX;
    const int m0 = bi * 128, n0 = bj * 128;

    const int wm = (wid >> 2) * 32, wn = (wid & 3) * 32;
    const int qm = lane >> 2, qp = lane & 3;

    int rr[2], cc[2];
#pragma unroll
    for (int i = 0; i < 2; i++) { int idx = tid + 512 * i; rr[i] = idx >> 3; cc[i] = (idx & 7) * 4; }

    float acc[2][4][4];
#pragma unroll
    for (int i = 0; i < 2; i++)
#pragma unroll
        for (int j = 0; j < 4; j++)
#pragma unroll
            for (int k = 0; k < 4; k++) acc[i][j][k] = 0.f;

    float4 ra[2], rb[2];
#pragma unroll
    for (int i = 0; i < 2; i++) {
        ra[i] = *(const float4*)(q + (size_t)(m0 + rr[i]) * NPIX + cc[i]);
        rb[i] = *(const float4*)(q + (size_t)(n0 + rr[i]) * NPIX + cc[i]);
    }
#pragma unroll
    for (int i = 0; i < 2; i++) {
        int off = rr[i] * RS + cc[i];
        split_store(sm + off,          sm + ET + off,     ra[i]);
        split_store(sm + 2 * ET + off, sm + 3 * ET + off, rb[i]);
    }
    __syncthreads();

    int s = 0;
    constexpr int NCH = NPIX / 32;   // 128
    for (int it = 0; it < NCH; ++it) {
        if (it + 1 < NCH) {
            const int k0 = (it + 1) * 32;
#pragma unroll
            for (int i = 0; i < 2; i++) {
                ra[i] = *(const float4*)(q + (size_t)(m0 + rr[i]) * NPIX + k0 + cc[i]);
                rb[i] = *(const float4*)(q + (size_t)(n0 + rr[i]) * NPIX + k0 + cc[i]);
            }
        }
        {
            const uint32_t* AH = sm + s * ESTAGE;
            const uint32_t* AL = AH + ET;
            const uint32_t* BH = AH + 2 * ET;
            const uint32_t* BL = AH + 3 * ET;
#pragma unroll
            for (int kk = 0; kk < 32; kk += 8) {
                uint32_t ah[2][4], al[2][4], bh[4][2], bl[4][2];
#pragma unroll
                for (int j = 0; j < 4; j++) {
                    const int ro = (wn + j * 8 + qm) * RS + kk + qp;
                    bh[j][0] = BH[ro]; bh[j][1] = BH[ro + 4];
                    bl[j][0] = BL[ro]; bl[j][1] = BL[ro + 4];
                }
#pragma unroll
                for (int i = 0; i < 2; i++) {
                    const int ro = (wm + i * 16 + qm) * RS + kk + qp;
                    ah[i][0] = AH[ro]; ah[i][1] = AH[ro + 8 * RS];
                    ah[i][2] = AH[ro + 4]; ah[i][3] = AH[ro + 8 * RS + 4];
                    al[i][0] = AL[ro]; al[i][1] = AL[ro + 8 * RS];
                    al[i][2] = AL[ro + 4]; al[i][3] = AL[ro + 8 * RS + 4];
                }
#pragma unroll
                for (int i = 0; i < 2; i++)
#pragma unroll
                    for (int j = 0; j < 4; j++) mma8(acc[i][j], ah[i], bh[j]);
#pragma unroll
                for (int i = 0; i < 2; i++)
#pragma unroll
                    for (int j = 0; j < 4; j++) mma8(acc[i][j], ah[i], bl[j]);
#pragma unroll
                for (int i = 0; i < 2; i++)
#pragma unroll
                    for (int j = 0; j < 4; j++) mma8(acc[i][j], al[i], bh[j]);
            }
        }
        if (it + 1 < NCH) {
            __syncthreads();
            uint32_t* S = sm + (s ^ 1) * ESTAGE;
#pragma unroll
            for (int i = 0; i < 2; i++) {
                int off = rr[i] * RS + cc[i];
                split_store(S + off,          S + ET + off,     ra[i]);
                split_store(S + 2 * ET + off, S + 3 * ET + off, rb[i]);
            }
            __syncthreads();
            s ^= 1;
        }
    }

    float* E = g_energy + (size_t)b * CCH * CCH;
    const bool mir = (bi != bj);
#pragma unroll
    for (int i = 0; i < 2; i++)
#pragma unroll
        for (int j = 0; j < 4; j++) {
            const int m = m0 + wm + i * 16 + qm;
            const int n = n0 + wn + j * 8 + qp * 2;
            float2 v0 = make_float2(acc[i][j][0], acc[i][j][1]);
            float2 v1 = make_float2(acc[i][j][2], acc[i][j][3]);
            *(float2*)&E[(size_t)m * CCH + n]       = v0;
            *(float2*)&E[(size_t)(m + 8) * CCH + n] = v1;
            if (mir) {
                E[(size_t)n * CCH + m]           = v0.x;
                E[(size_t)(n + 1) * CCH + m]     = v0.y;
                E[(size_t)n * CCH + m + 8]       = v1.x;
                E[(size_t)(n + 1) * CCH + m + 8] = v1.y;
            }
        }
}

// ---------------------------------------------------------------------------
// Kernel 2: in-place row softmax of exp(rowmin - e)/sum  (== softmax(max - e))
// ---------------------------------------------------------------------------
__global__ __launch_bounds__(256) void softmax_kernel()
{
    const int row  = blockIdx.x * 8 + (threadIdx.x >> 5);
    const int lane = threadIdx.x & 31;
    float* e = g_energy + (size_t)row * CCH;

    float v[16];
    float mn = 3.4e38f;
#pragma unroll
    for (int i = 0; i < 16; i++) { v[i] = e[lane + i * 32]; mn = fminf(mn, v[i]); }
#pragma unroll
    for (int o = 16; o > 0; o >>= 1)
        mn = fminf(mn, __shfl_xor_sync(0xffffffffu, mn, o));
    float s = 0.f;
#pragma unroll
    for (int i = 0; i < 16; i++) { v[i] = expf(mn - v[i]); s += v[i]; }
#pragma unroll
    for (int o = 16; o > 0; o >>= 1)
        s += __shfl_xor_sync(0xffffffffu, s, o);
    const float r = 1.0f / s;
#pragma unroll
    for (int i = 0; i < 16; i++) e[lane + i * 32] = v[i] * r;
}

// ---------------------------------------------------------------------------
// Kernel 3: y[b] = gamma * (attn[b] @ q[b]) + x[b]   (3xTF32)
// 512 thr, warps 4x4, warp tile 32x32. A m-major RS=36; B k-major [32][136].
// ---------------------------------------------------------------------------
#define BRS 136
#define OT_B (32 * BRS)                       // 4352 u32
#define OSTAGE (2 * ET + 2 * OT_B)            // 17920 u32
#define OSMEM_BYTES (2 * OSTAGE * 4)          // 143360

__global__ __launch_bounds__(512) void out_kernel(const float* __restrict__ x,
                                                  const float* __restrict__ gamma,
                                                  float* __restrict__ out)
{
    extern __shared__ uint32_t sm[];
    const int tid = threadIdx.x, lane = tid & 31, wid = tid >> 5;
    const int b = blockIdx.z;
    const float* A = g_energy + (size_t)b * CCH * CCH;
    const float* q = x + (size_t)b * CCH * NPIX;
    const int m0 = blockIdx.y * 128;
    const int n0 = blockIdx.x * 128;

    const int wm = (wid >> 2) * 32, wn = (wid & 3) * 32;
    const int qm = lane >> 2, qp = lane & 3;

    int ar[2], ac[2], bk[2], bn[2];
#pragma unroll
    for (int i = 0; i < 2; i++) {
        int idx = tid + 512 * i;
        ar[i] = idx >> 3;  ac[i] = (idx & 7) * 4;    // A tile 128x32
        bk[i] = idx >> 5;  bn[i] = (idx & 31) * 4;   // B tile 32x128
    }

    float acc[2][4][4];
#pragma unroll
    for (int i = 0; i < 2; i++)
#pragma unroll
        for (int j = 0; j < 4; j++)
#pragma unroll
            for (int k = 0; k < 4; k++) acc[i][j][k] = 0.f;

    float4 ra[2], rb[2];
#pragma unroll
    for (int i = 0; i < 2; i++) {
        ra[i] = *(const float4*)(A + (size_t)(m0 + ar[i]) * CCH + ac[i]);
        rb[i] = *(const float4*)(q + (size_t)bk[i] * NPIX + n0 + bn[i]);
    }
#pragma unroll
    for (int i = 0; i < 2; i++) {
        int aoff = ar[i] * RS + ac[i];
        int boff = bk[i] * BRS + bn[i];
        split_store(sm + aoff,          sm + ET + aoff,          ra[i]);
        split_store(sm + 2 * ET + boff, sm + 2 * ET + OT_B + boff, rb[i]);
    }
    __syncthreads();

    int s = 0;
    constexpr int NCH = CCH / 32;   // 16
    for (int it = 0; it < NCH; ++it) {
        if (it + 1 < NCH) {
            const int k0 = (it + 1) * 32;
#pragma unroll
            for (int i = 0; i < 2; i++) {
                ra[i] = *(const float4*)(A + (size_t)(m0 + ar[i]) * CCH + k0 + ac[i]);
                rb[i] = *(const float4*)(q + (size_t)(k0 + bk[i]) * NPIX + n0 + bn[i]);
            }
        }
        {
            const uint32_t* AH = sm + s * OSTAGE;
            const uint32_t* AL = AH + ET;
            const uint32_t* BH = AH + 2 * ET;
            const uint32_t* BL = BH + OT_B;
#pragma unroll
            for (int kk = 0; kk < 32; kk += 8) {
                uint32_t ah[2][4], al[2][4], bh[4][2], bl[4][2];
#pragma unroll
                for (int j = 0; j < 4; j++) {
                    const int co = wn + j * 8 + qm;
                    bh[j][0] = BH[(kk + qp) * BRS + co];
                    bh[j][1] = BH[(kk + 4 + qp) * BRS + co];
                    bl[j][0] = BL[(kk + qp) * BRS + co];
                    bl[j][1] = BL[(kk + 4 + qp) * BRS + co];
                }
#pragma unroll
                for (int i = 0; i < 2; i++) {
                    const int ro = (wm + i * 16 + qm) * RS + kk + qp;
                    ah[i][0] = AH[ro]; ah[i][1] = AH[ro + 8 * RS];
                    ah[i][2] = AH[ro + 4]; ah[i][3] = AH[ro + 8 * RS + 4];
                    al[i][0] = AL[ro]; al[i][1] = AL[ro + 8 * RS];
                    al[i][2] = AL[ro + 4]; al[i][3] = AL[ro + 8 * RS + 4];
                }
#pragma unroll
                for (int i = 0; i < 2; i++)
#pragma unroll
                    for (int j = 0; j < 4; j++) mma8(acc[i][j], ah[i], bh[j]);
#pragma unroll
                for (int i = 0; i < 2; i++)
#pragma unroll
                    for (int j = 0; j < 4; j++) mma8(acc[i][j], ah[i], bl[j]);
#pragma unroll
                for (int i = 0; i < 2; i++)
#pragma unroll
                    for (int j = 0; j < 4; j++) mma8(acc[i][j], al[i], bh[j]);
            }
        }
        if (it + 1 < NCH) {
            __syncthreads();
            uint32_t* S = sm + (s ^ 1) * OSTAGE;
#pragma unroll
            for (int i = 0; i < 2; i++) {
                int aoff = ar[i] * RS + ac[i];
                int boff = bk[i] * BRS + bn[i];
                split_store(S + aoff,          S + ET + aoff,          ra[i]);
                split_store(S + 2 * ET + boff, S + 2 * ET + OT_B + boff, rb[i]);
            }
            __syncthreads();
            s ^= 1;
        }
    }

    const float g = *gamma;
#pragma unroll
    for (int i = 0; i < 2; i++)
#pragma unroll
        for (int j = 0; j < 4; j++) {
            const int m = m0 + wm + i * 16 + qm;
            const int n = n0 + wn + j * 8 + qp * 2;
            {
                const size_t p = (size_t)(b * CCH + m) * NPIX + n;
                float2 xv = *(const float2*)(x + p);
                float2 o;
                o.x = fmaf(g, acc[i][j][0], xv.x);
                o.y = fmaf(g, acc[i][j][1], xv.y);
                *(float2*)(out + p) = o;
            }
            {
                const size_t p = (size_t)(b * CCH + m + 8) * NPIX + n;
                float2 xv = *(const float2*)(x + p);
                float2 o;
                o.x = fmaf(g, acc[i][j][2], xv.x);
                o.y = fmaf(g, acc[i][j][3], xv.y);
                *(float2*)(out + p) = o;
            }
        }
}

// ---------------------------------------------------------------------------
extern "C" void kernel_launch(void* const* d_in, const int* in_sizes, int n_in,
                              void* d_out, int out_size)
{
    const float* x     = (const float*)d_in[0];
    const float* gamma = (const float*)d_in[1];
    float* out = (float*)d_out;

    cudaFuncSetAttribute(energy_kernel,
                         cudaFuncAttributeMaxDynamicSharedMemorySize, ESMEM_BYTES);
    cudaFuncSetAttribute(out_kernel,
                         cudaFuncAttributeMaxDynamicSharedMemorySize, OSMEM_BYTES);

    energy_kernel<<<dim3(10, BATCH), 512, ESMEM_BYTES>>>(x);
    softmax_kernel<<<(BATCH * CCH) / 8, 256>>>();
    out_kernel<<<dim3(NPIX / 128, CCH / 128, BATCH), 512, OSMEM_BYTES>>>(x, gamma, out);
}

// round 5
// speedup vs baseline: 1.5157x; 1.5157x over previous
#include <cuda_runtime.h>
#include <cstdint>

#define BATCH 16
#define CCH   512
#define NPIX  4096

// attention / energy scratch: 16 MB
__device__ float g_energy[(size_t)BATCH * CCH * CCH];

// ---------------------------------------------------------------------------
// helpers
// ---------------------------------------------------------------------------
__device__ __forceinline__ uint32_t hi_tf32(float x) {
    return __float_as_uint(x) & 0xFFFFE000u;   // exact tf32 (top 19 bits)
}
__device__ __forceinline__ uint32_t lo_tf32(float x, uint32_t hibits) {
    float lo = x - __uint_as_float(hibits);
    uint32_t r;
    asm("cvt.rna.tf32.f32 %0, %1;" : "=r"(r) : "f"(lo));
    return r;
}
__device__ __forceinline__ uint32_t rna_tf32(float x) {
    uint32_t r;
    asm("cvt.rna.tf32.f32 %0, %1;" : "=r"(r) : "f"(x));
    return r;
}
__device__ __forceinline__ void mma8(float* d, const uint32_t* a, const uint32_t* b) {
    asm volatile(
        "mma.sync.aligned.m16n8k8.row.col.f32.tf32.tf32.f32 "
        "{%0,%1,%2,%3}, {%4,%5,%6,%7}, {%8,%9}, {%0,%1,%2,%3};"
        : "+f"(d[0]), "+f"(d[1]), "+f"(d[2]), "+f"(d[3])
        : "r"(a[0]), "r"(a[1]), "r"(a[2]), "r"(a[3]), "r"(b[0]), "r"(b[1]));
}
__device__ __forceinline__ void split_store(uint32_t* dH, uint32_t* dL, float4 v) {
    uint4 h, l;
    h.x = hi_tf32(v.x); h.y = hi_tf32(v.y); h.z = hi_tf32(v.z); h.w = hi_tf32(v.w);
    l.x = lo_tf32(v.x, h.x); l.y = lo_tf32(v.y, h.y);
    l.z = lo_tf32(v.z, h.z); l.w = lo_tf32(v.w, h.w);
    *(uint4*)dH = h;
    *(uint4*)dL = l;
}
__device__ __forceinline__ void rna_store(uint32_t* d, float4 v) {
    uint4 h;
    h.x = rna_tf32(v.x); h.y = rna_tf32(v.y); h.z = rna_tf32(v.z); h.w = rna_tf32(v.w);
    *(uint4*)d = h;
}

#define RS 36                 // m-major row stride (floats), conflict-free

// ---------------------------------------------------------------------------
// Kernel 1: energy[b] = q qᵀ  (3xTF32, symmetric: 36 upper 64x64 blocks)
// 128 thr (4 warps 2x2, warp tile 32x32), BK=32, double-buffered hi/lo smem.
// 576 CTAs, 3 CTAs/SM -> no wave tail.
// ---------------------------------------------------------------------------
#define ET64   (64 * RS)                  // 2304 u32 per 64x32 tile
#define ESTAGE (4 * ET64)                 // AH|AL|BH|BL = 9216 u32
#define ESMEM_BYTES (2 * ESTAGE * 4)      // 73728

__global__ __launch_bounds__(128) void energy_kernel(const float* __restrict__ x)
{
    extern __shared__ uint32_t sm[];
    const int tid = threadIdx.x, lane = tid & 31, wid = tid >> 5;
    const int b = blockIdx.y;

    // upper-triangle pair (bi <= bj) of 64-blocks from blockIdx.x in [0,36)
    int bi = 0, t = blockIdx.x, rowlen = 8;
    while (t >= rowlen) { t -= rowlen; bi++; rowlen--; }
    const int bj = bi + t;

    const float* q = x + (size_t)b * CCH * NPIX;
    const int m0 = bi * 64, n0 = bj * 64;

    const int wm = (wid >> 1) * 32, wn = (wid & 1) * 32;
    const int qm = lane >> 2, qp = lane & 3;

    int rr[4], cc[4];
#pragma unroll
    for (int i = 0; i < 4; i++) { int idx = tid + 128 * i; rr[i] = idx >> 3; cc[i] = (idx & 7) * 4; }

    float acc[2][4][4];
#pragma unroll
    for (int i = 0; i < 2; i++)
#pragma unroll
        for (int j = 0; j < 4; j++)
#pragma unroll
            for (int k = 0; k < 4; k++) acc[i][j][k] = 0.f;

    float4 ra[4], rb[4];
#pragma unroll
    for (int i = 0; i < 4; i++) {
        ra[i] = *(const float4*)(q + (size_t)(m0 + rr[i]) * NPIX + cc[i]);
        rb[i] = *(const float4*)(q + (size_t)(n0 + rr[i]) * NPIX + cc[i]);
    }
#pragma unroll
    for (int i = 0; i < 4; i++) {
        int off = rr[i] * RS + cc[i];
        split_store(sm + off,            sm + ET64 + off,     ra[i]);
        split_store(sm + 2 * ET64 + off, sm + 3 * ET64 + off, rb[i]);
    }
    __syncthreads();

    int s = 0;
    constexpr int NCH = NPIX / 32;   // 128
    for (int it = 0; it < NCH; ++it) {
        if (it + 1 < NCH) {
            const int k0 = (it + 1) * 32;
#pragma unroll
            for (int i = 0; i < 4; i++) {
                ra[i] = *(const float4*)(q + (size_t)(m0 + rr[i]) * NPIX + k0 + cc[i]);
                rb[i] = *(const float4*)(q + (size_t)(n0 + rr[i]) * NPIX + k0 + cc[i]);
            }
        }
        {
            const uint32_t* AH = sm + s * ESTAGE;
            const uint32_t* AL = AH + ET64;
            const uint32_t* BH = AH + 2 * ET64;
            const uint32_t* BL = AH + 3 * ET64;
#pragma unroll
            for (int kk = 0; kk < 32; kk += 8) {
                uint32_t ah[2][4], al[2][4], bh[4][2], bl[4][2];
#pragma unroll
                for (int j = 0; j < 4; j++) {
                    const int ro = (wn + j * 8 + qm) * RS + kk + qp;
                    bh[j][0] = BH[ro]; bh[j][1] = BH[ro + 4];
                    bl[j][0] = BL[ro]; bl[j][1] = BL[ro + 4];
                }
#pragma unroll
                for (int i = 0; i < 2; i++) {
                    const int ro = (wm + i * 16 + qm) * RS + kk + qp;
                    ah[i][0] = AH[ro]; ah[i][1] = AH[ro + 8 * RS];
                    ah[i][2] = AH[ro + 4]; ah[i][3] = AH[ro + 8 * RS + 4];
                    al[i][0] = AL[ro]; al[i][1] = AL[ro + 8 * RS];
                    al[i][2] = AL[ro + 4]; al[i][3] = AL[ro + 8 * RS + 4];
                }
#pragma unroll
                for (int i = 0; i < 2; i++)
#pragma unroll
                    for (int j = 0; j < 4; j++) mma8(acc[i][j], ah[i], bh[j]);
#pragma unroll
                for (int i = 0; i < 2; i++)
#pragma unroll
                    for (int j = 0; j < 4; j++) mma8(acc[i][j], ah[i], bl[j]);
#pragma unroll
                for (int i = 0; i < 2; i++)
#pragma unroll
                    for (int j = 0; j < 4; j++) mma8(acc[i][j], al[i], bh[j]);
            }
        }
        if (it + 1 < NCH) {
            __syncthreads();
            uint32_t* S = sm + (s ^ 1) * ESTAGE;
#pragma unroll
            for (int i = 0; i < 4; i++) {
                int off = rr[i] * RS + cc[i];
                split_store(S + off,            S + ET64 + off,     ra[i]);
                split_store(S + 2 * ET64 + off, S + 3 * ET64 + off, rb[i]);
            }
            __syncthreads();
            s ^= 1;
        }
    }

    float* E = g_energy + (size_t)b * CCH * CCH;
    const bool mir = (bi != bj);
#pragma unroll
    for (int i = 0; i < 2; i++)
#pragma unroll
        for (int j = 0; j < 4; j++) {
            const int m = m0 + wm + i * 16 + qm;
            const int n = n0 + wn + j * 8 + qp * 2;
            float2 v0 = make_float2(acc[i][j][0], acc[i][j][1]);
            float2 v1 = make_float2(acc[i][j][2], acc[i][j][3]);
            *(float2*)&E[(size_t)m * CCH + n]       = v0;
            *(float2*)&E[(size_t)(m + 8) * CCH + n] = v1;
            if (mir) {
                E[(size_t)n * CCH + m]           = v0.x;
                E[(size_t)(n + 1) * CCH + m]     = v0.y;
                E[(size_t)n * CCH + m + 8]       = v1.x;
                E[(size_t)(n + 1) * CCH + m + 8] = v1.y;
            }
        }
}

// ---------------------------------------------------------------------------
// Kernel 2: in-place row softmax of exp(rowmin - e)/sum  (== softmax(max - e))
// ---------------------------------------------------------------------------
__global__ __launch_bounds__(256) void softmax_kernel()
{
    const int row  = blockIdx.x * 8 + (threadIdx.x >> 5);
    const int lane = threadIdx.x & 31;
    float* e = g_energy + (size_t)row * CCH;

    float v[16];
    float mn = 3.4e38f;
#pragma unroll
    for (int i = 0; i < 16; i++) { v[i] = e[lane + i * 32]; mn = fminf(mn, v[i]); }
#pragma unroll
    for (int o = 16; o > 0; o >>= 1)
        mn = fminf(mn, __shfl_xor_sync(0xffffffffu, mn, o));
    float s = 0.f;
#pragma unroll
    for (int i = 0; i < 16; i++) { v[i] = expf(mn - v[i]); s += v[i]; }
#pragma unroll
    for (int o = 16; o > 0; o >>= 1)
        s += __shfl_xor_sync(0xffffffffu, s, o);
    const float r = 1.0f / s;
#pragma unroll
    for (int i = 0; i < 16; i++) e[lane + i * 32] = v[i] * r;
}

// ---------------------------------------------------------------------------
// Kernel 3: y[b] = gamma * (attn[b] @ q[b]) + x[b]   (2-pass TF32)
// A = attn rounded rna->tf32 (no lo); B = q hi+lo. 512 thr, warps 4x4.
// ---------------------------------------------------------------------------
#define ET (128 * RS)                         // 4608 u32
#define BRS 136
#define OT_B (32 * BRS)                       // 4352 u32
#define OSTAGE (ET + 2 * OT_B)                // 13312 u32
#define OSMEM_BYTES (2 * OSTAGE * 4)          // 106496

__global__ __launch_bounds__(512) void out_kernel(const float* __restrict__ x,
                                                  const float* __restrict__ gamma,
                                                  float* __restrict__ out)
{
    extern __shared__ uint32_t sm[];
    const int tid = threadIdx.x, lane = tid & 31, wid = tid >> 5;
    const int b = blockIdx.z;
    const float* A = g_energy + (size_t)b * CCH * CCH;
    const float* q = x + (size_t)b * CCH * NPIX;
    const int m0 = blockIdx.y * 128;
    const int n0 = blockIdx.x * 128;

    const int wm = (wid >> 2) * 32, wn = (wid & 3) * 32;
    const int qm = lane >> 2, qp = lane & 3;

    int ar[2], ac[2], bk[2], bn[2];
#pragma unroll
    for (int i = 0; i < 2; i++) {
        int idx = tid + 512 * i;
        ar[i] = idx >> 3;  ac[i] = (idx & 7) * 4;    // A tile 128x32
        bk[i] = idx >> 5;  bn[i] = (idx & 31) * 4;   // B tile 32x128
    }

    float acc[2][4][4];
#pragma unroll
    for (int i = 0; i < 2; i++)
#pragma unroll
        for (int j = 0; j < 4; j++)
#pragma unroll
            for (int k = 0; k < 4; k++) acc[i][j][k] = 0.f;

    float4 ra[2], rb[2];
#pragma unroll
    for (int i = 0; i < 2; i++) {
        ra[i] = *(const float4*)(A + (size_t)(m0 + ar[i]) * CCH + ac[i]);
        rb[i] = *(const float4*)(q + (size_t)bk[i] * NPIX + n0 + bn[i]);
    }
#pragma unroll
    for (int i = 0; i < 2; i++) {
        int aoff = ar[i] * RS + ac[i];
        int boff = bk[i] * BRS + bn[i];
        rna_store(sm + aoff, ra[i]);
        split_store(sm + ET + boff, sm + ET + OT_B + boff, rb[i]);
    }
    __syncthreads();

    int s = 0;
    constexpr int NCH = CCH / 32;   // 16
    for (int it = 0; it < NCH; ++it) {
        if (it + 1 < NCH) {
            const int k0 = (it + 1) * 32;
#pragma unroll
            for (int i = 0; i < 2; i++) {
                ra[i] = *(const float4*)(A + (size_t)(m0 + ar[i]) * CCH + k0 + ac[i]);
                rb[i] = *(const float4*)(q + (size_t)(k0 + bk[i]) * NPIX + n0 + bn[i]);
            }
        }
        {
            const uint32_t* AH = sm + s * OSTAGE;
            const uint32_t* BH = AH + ET;
            const uint32_t* BL = BH + OT_B;
#pragma unroll
            for (int kk = 0; kk < 32; kk += 8) {
                uint32_t ah[2][4], bh[4][2], bl[4][2];
#pragma unroll
                for (int j = 0; j < 4; j++) {
                    const int co = wn + j * 8 + qm;
                    bh[j][0] = BH[(kk + qp) * BRS + co];
                    bh[j][1] = BH[(kk + 4 + qp) * BRS + co];
                    bl[j][0] = BL[(kk + qp) * BRS + co];
                    bl[j][1] = BL[(kk + 4 + qp) * BRS + co];
                }
#pragma unroll
                for (int i = 0; i < 2; i++) {
                    const int ro = (wm + i * 16 + qm) * RS + kk + qp;
                    ah[i][0] = AH[ro]; ah[i][1] = AH[ro + 8 * RS];
                    ah[i][2] = AH[ro + 4]; ah[i][3] = AH[ro + 8 * RS + 4];
                }
#pragma unroll
                for (int i = 0; i < 2; i++)
#pragma unroll
                    for (int j = 0; j < 4; j++) mma8(acc[i][j], ah[i], bh[j]);
#pragma unroll
                for (int i = 0; i < 2; i++)
#pragma unroll
                    for (int j = 0; j < 4; j++) mma8(acc[i][j], ah[i], bl[j]);
            }
        }
        if (it + 1 < NCH) {
            __syncthreads();
            uint32_t* S = sm + (s ^ 1) * OSTAGE;
#pragma unroll
            for (int i = 0; i < 2; i++) {
                int aoff = ar[i] * RS + ac[i];
                int boff = bk[i] * BRS + bn[i];
                rna_store(S + aoff, ra[i]);
                split_store(S + ET + boff, S + ET + OT_B + boff, rb[i]);
            }
            __syncthreads();
            s ^= 1;
        }
    }

    const float g = *gamma;
#pragma unroll
    for (int i = 0; i < 2; i++)
#pragma unroll
        for (int j = 0; j < 4; j++) {
            const int m = m0 + wm + i * 16 + qm;
            const int n = n0 + wn + j * 8 + qp * 2;
            {
                const size_t p = (size_t)(b * CCH + m) * NPIX + n;
                float2 xv = *(const float2*)(x + p);
                float2 o;
                o.x = fmaf(g, acc[i][j][0], xv.x);
                o.y = fmaf(g, acc[i][j][1], xv.y);
                *(float2*)(out + p) = o;
            }
            {
                const size_t p = (size_t)(b * CCH + m + 8) * NPIX + n;
                float2 xv = *(const float2*)(x + p);
                float2 o;
                o.x = fmaf(g, acc[i][j][2], xv.x);
                o.y = fmaf(g, acc[i][j][3], xv.y);
                *(float2*)(out + p) = o;
            }
        }
}

// ---------------------------------------------------------------------------
extern "C" void kernel_launch(void* const* d_in, const int* in_sizes, int n_in,
                              void* d_out, int out_size)
{
    const float* x     = (const float*)d_in[0];
    const float* gamma = (const float*)d_in[1];
    float* out = (float*)d_out;

    cudaFuncSetAttribute(energy_kernel,
                         cudaFuncAttributeMaxDynamicSharedMemorySize, ESMEM_BYTES);
    cudaFuncSetAttribute(out_kernel,
                         cudaFuncAttributeMaxDynamicSharedMemorySize, OSMEM_BYTES);

    energy_kernel<<<dim3(36, BATCH), 128, ESMEM_BYTES>>>(x);
    softmax_kernel<<<(BATCH * CCH) / 8, 256>>>();
    out_kernel<<<dim3(NPIX / 128, CCH / 128, BATCH), 512, OSMEM_BYTES>>>(x, gamma, out);
}